// round 10
// baseline (speedup 1.0000x reference)
#include <cuda_runtime.h>
#include <cuda_fp16.h>
#include <math_constants.h>
#include <cstdint>

// Problem dims (fixed by the reference)
#define B_  16
#define L_  2048
#define DH  1280
#define T_  512
#define DG  768
#define P_  256
#define SCALE_ 0.0625f   // 256^-0.5

typedef __half fp16;

// ---------------- device-global scratch (allocation-free rule) --------------
__device__ __align__(16) fp16 g_Kf [(long)B_ * L_ * P_];   // K fp16
__device__ __align__(16) fp16 g_Qf [(long)B_ * T_ * P_];   // Q fp16
__device__ __align__(16) float g_S [(long)B_ * T_ * L_];   // logits fp32
__device__ __align__(16) fp16 g_Sf [(long)B_ * T_ * L_];   // probs fp16

// ---------------------------------------------------------------------------
// fp16 tensor-core GEMM; per-operand source dtype:
//   CVT_A / CVT_B = true  : operand is fp32 in gmem; converted to fp16 during
//                           smem staging (immediate ld->cvt->st, no cp.async)
//                  = false : operand already fp16; staged via cp.async.cg
//   TRANS_B = true : C = alpha * A[M,K] @ B[N,K]^T   (NT; K-major)
//   TRANS_B = false: C = alpha * A[M,K] @ B[K,N]     (NN; ldmatrix.trans)
//   fp32 accumulate. EPI=0: fp32 C (alpha applied). EPI=1: fp16 C.
// BM=128, BN=128, BK=64, 256 threads = 8 warps (2M x 4N), warp tile 64x32,
// double-buffered smem, 2 CTAs/SM.
// ---------------------------------------------------------------------------
#define BM 128
#define BN 128
#define BK 64
#define SK 72                      // NT row stride (halves)
#define BNP 136                    // NN B row stride (halves), 272B
#define STAGE_A (BM * SK)          // 9216 halves
#define STAGE_B_NT (BN * SK)       // 9216
#define STAGE_B_NN (BK * BNP)      // 8704
#define BUF_NT (STAGE_A + STAGE_B_NT)
#define BUF_NN (STAGE_A + STAGE_B_NN)
#define SMEM_NT (2 * BUF_NT * 2)   // 73728 B
#define SMEM_NN (2 * BUF_NN * 2)   // 71680 B

__device__ __forceinline__ uint32_t smem_a32(const void* p) {
    return (uint32_t)__cvta_generic_to_shared(p);
}

__device__ __forceinline__ void cpa16(uint32_t d, const void* s) {
    asm volatile("cp.async.cg.shared.global [%0], [%1], 16;" :: "r"(d), "l"(s));
}
__device__ __forceinline__ void cpa_commit() {
    asm volatile("cp.async.commit_group;" ::: "memory");
}
__device__ __forceinline__ void cpa_wait0() {
    asm volatile("cp.async.wait_group 0;" ::: "memory");
}

// load 8 fp32, convert, store 16B of fp16 into smem (immediate staging)
__device__ __forceinline__ void cvt_st8(fp16* dst, const float* src) {
    const float4 a = *(const float4*)src;
    const float4 b = *(const float4*)(src + 4);
    __half2 h0 = __floats2half2_rn(a.x, a.y);
    __half2 h1 = __floats2half2_rn(a.z, a.w);
    __half2 h2 = __floats2half2_rn(b.x, b.y);
    __half2 h3 = __floats2half2_rn(b.z, b.w);
    uint4 v;
    v.x = *(uint32_t*)&h0; v.y = *(uint32_t*)&h1;
    v.z = *(uint32_t*)&h2; v.w = *(uint32_t*)&h3;
    *(uint4*)dst = v;
}

__device__ __forceinline__ void ldm4(uint32_t a, uint32_t& r0, uint32_t& r1,
                                     uint32_t& r2, uint32_t& r3) {
    asm volatile("ldmatrix.sync.aligned.m8n8.x4.shared.b16 {%0,%1,%2,%3}, [%4];\n"
                 : "=r"(r0), "=r"(r1), "=r"(r2), "=r"(r3) : "r"(a));
}
__device__ __forceinline__ void ldm4t(uint32_t a, uint32_t& r0, uint32_t& r1,
                                      uint32_t& r2, uint32_t& r3) {
    asm volatile("ldmatrix.sync.aligned.m8n8.x4.trans.shared.b16 {%0,%1,%2,%3}, [%4];\n"
                 : "=r"(r0), "=r"(r1), "=r"(r2), "=r"(r3) : "r"(a));
}

__device__ __forceinline__ void mma16816(float* c, const uint32_t* a,
                                         uint32_t b0, uint32_t b1) {
    asm volatile(
        "mma.sync.aligned.m16n8k16.row.col.f32.f16.f16.f32 "
        "{%0,%1,%2,%3}, {%4,%5,%6,%7}, {%8,%9}, {%0,%1,%2,%3};\n"
        : "+f"(c[0]), "+f"(c[1]), "+f"(c[2]), "+f"(c[3])
        : "r"(a[0]), "r"(a[1]), "r"(a[2]), "r"(a[3]), "r"(b0), "r"(b1));
}

template <int EPI, bool TRANS_B, bool CVT_A, bool CVT_B>
__global__ void __launch_bounds__(256, 2)
gemm_fp16(const void* __restrict__ Av, const void* __restrict__ Bv,
          float* __restrict__ Cf, fp16* __restrict__ Ch,
          int K, int N, long sA, long sB, long sC, float alpha)
{
    constexpr int BUF = TRANS_B ? BUF_NT : BUF_NN;
    constexpr bool USE_CPA = (!CVT_A) || (!CVT_B);
    extern __shared__ fp16 sm[];   // [2][BUF]

    const long bz = blockIdx.z;
    const float* Af = (const float*)Av + (CVT_A ? bz * sA : 0);
    const fp16*  Ah = (const fp16*)Av + (CVT_A ? 0 : bz * sA);
    const float* Bf = (const float*)Bv + (CVT_B ? bz * sB : 0);
    const fp16*  Bh = (const fp16*)Bv + (CVT_B ? 0 : bz * sB);

    const int m0 = blockIdx.y * BM;
    const int n0 = blockIdx.x * BN;

    const int tid  = threadIdx.x;
    const int lane = tid & 31;
    const int wid  = tid >> 5;
    const int wm = (wid & 1) * 64;    // warp M offset
    const int wn = (wid >> 1) * 32;   // warp N offset

    const int srow = tid >> 3;        // 0..31 (+ i*32)
    const int scc  = (tid & 7) * 8;   // element offset within row (8 per chunk)

    float acc[4][4][4];
#pragma unroll
    for (int i = 0; i < 4; i++)
#pragma unroll
        for (int j = 0; j < 4; j++)
#pragma unroll
            for (int q = 0; q < 4; q++) acc[i][j][q] = 0.0f;

    const uint32_t smBase = smem_a32(sm);
    const uint32_t aBase = smBase +
        (uint32_t)(((wm + (lane & 15)) * SK + (lane >> 4) * 8) * 2);
    const int bg = lane >> 3, br = lane & 7;
    const uint32_t bBaseNT = smBase + (uint32_t)(STAGE_A * 2) +
        (uint32_t)(((wn + (bg >> 1) * 8 + br) * SK + (bg & 1) * 8) * 2);
    const uint32_t bBaseNN = smBase + (uint32_t)(STAGE_A * 2) +
        (uint32_t)((((bg & 1) * 8 + br) * BNP + wn + (bg >> 1) * 8) * 2);

    const int nk = K / BK;

    auto stage = [&](int kt, int buf) {
        const long k0 = (long)kt * BK;
        fp16* dstA = sm + buf * BUF;
        const uint32_t dA = smBase + (uint32_t)(buf * BUF * 2);
        // ---- A tile [BM rows][BK halves] ----
#pragma unroll
        for (int i = 0; i < 4; i++) {
            const int row = srow + i * 32;
            const int off = row * SK + scc;
            if (CVT_A)
                cvt_st8(dstA + off, Af + (long)(m0 + row) * K + k0 + scc);
            else
                cpa16(dA + (uint32_t)(off * 2),
                      Ah + (long)(m0 + row) * K + k0 + scc);
        }
        // ---- B tile ----
        fp16* dstB = dstA + STAGE_A;
        const uint32_t dB = dA + (uint32_t)(STAGE_A * 2);
        if (TRANS_B) {
#pragma unroll
            for (int i = 0; i < 4; i++) {
                const int row = srow + i * 32;
                const int off = row * SK + scc;
                if (CVT_B)
                    cvt_st8(dstB + off, Bf + (long)(n0 + row) * K + k0 + scc);
                else
                    cpa16(dB + (uint32_t)(off * 2),
                          Bh + (long)(n0 + row) * K + k0 + scc);
            }
        } else {
            // B tile [BK=64 rows][128 elems] = 1024 chunks, 4/thread
#pragma unroll
            for (int i = 0; i < 4; i++) {
                const int ch = tid + i * 256;
                const int kr = ch >> 4;          // 0..63
                const int nc = (ch & 15) * 8;    // 0..120
                const int off = kr * BNP + nc;
                if (CVT_B)
                    cvt_st8(dstB + off, Bf + (k0 + kr) * (long)N + n0 + nc);
                else
                    cpa16(dB + (uint32_t)(off * 2),
                          Bh + (k0 + kr) * (long)N + n0 + nc);
            }
        }
    };

    stage(0, 0);
    if (USE_CPA) { cpa_commit(); cpa_wait0(); }
    __syncthreads();

    for (int kt = 0; kt < nk; kt++) {
        const int cur = kt & 1;
        const bool more = (kt + 1 < nk);
        if (more) {
            stage(kt + 1, 1 - cur);
            if (USE_CPA) cpa_commit();
        }

        const uint32_t bufOff = (uint32_t)(cur * (BUF * 2));
#pragma unroll
        for (int ks = 0; ks < 4; ks++) {
            uint32_t af[4][4], bf[2][4];
#pragma unroll
            for (int fm = 0; fm < 4; fm++)
                ldm4(aBase + bufOff + (uint32_t)(fm * (16 * SK * 2) + ks * 32),
                     af[fm][0], af[fm][1], af[fm][2], af[fm][3]);
            if (TRANS_B) {
#pragma unroll
                for (int f2 = 0; f2 < 2; f2++)
                    ldm4(bBaseNT + bufOff + (uint32_t)(f2 * (16 * SK * 2) + ks * 32),
                         bf[f2][0], bf[f2][1], bf[f2][2], bf[f2][3]);
            } else {
#pragma unroll
                for (int f2 = 0; f2 < 2; f2++)
                    ldm4t(bBaseNN + bufOff +
                              (uint32_t)(ks * (16 * BNP * 2) + f2 * 32),
                          bf[f2][0], bf[f2][1], bf[f2][2], bf[f2][3]);
            }
#pragma unroll
            for (int fm = 0; fm < 4; fm++)
#pragma unroll
                for (int fn = 0; fn < 4; fn++)
                    mma16816(acc[fm][fn], af[fm],
                             bf[fn >> 1][(fn & 1) * 2],
                             bf[fn >> 1][(fn & 1) * 2 + 1]);
        }

        if (more && USE_CPA) cpa_wait0();
        __syncthreads();
    }

    const int er = lane >> 2, ec = (lane & 3) * 2;
    if (EPI == 0) Cf += bz * sC; else Ch += bz * sC;
#pragma unroll
    for (int fm = 0; fm < 4; fm++) {
#pragma unroll
        for (int fn = 0; fn < 4; fn++) {
            const int row = m0 + wm + fm * 16 + er;
            const int col = n0 + wn + fn * 8 + ec;
            if (EPI == 0) {
                float2 v0 = {acc[fm][fn][0] * alpha, acc[fm][fn][1] * alpha};
                float2 v1 = {acc[fm][fn][2] * alpha, acc[fm][fn][3] * alpha};
                *(float2*)(Cf + (long)row * N + col) = v0;
                *(float2*)(Cf + (long)(row + 8) * N + col) = v1;
            } else {
                __half2 v0 = __floats2half2_rn(acc[fm][fn][0], acc[fm][fn][1]);
                __half2 v1 = __floats2half2_rn(acc[fm][fn][2], acc[fm][fn][3]);
                *(__half2*)(Ch + (long)row * N + col) = v0;
                *(__half2*)(Ch + (long)(row + 8) * N + col) = v1;
            }
        }
    }
}

// ---------------------------------------------------------------------------
// Row softmax over L_=2048 (fp32 logits in, fp16 probs out).
// ---------------------------------------------------------------------------
__global__ void __launch_bounds__(256)
softmax_rows(const float* __restrict__ S, fp16* __restrict__ Sf)
{
    const float* p = S + (long)blockIdx.x * L_;
    const int tid = threadIdx.x;

    float2 v[4];
    float m = -CUDART_INF_F;
#pragma unroll
    for (int i = 0; i < 4; i++) {
        v[i] = ((const float2*)p)[i * 256 + tid];
        m = fmaxf(m, fmaxf(v[i].x, v[i].y));
    }

    __shared__ float red[8];
#pragma unroll
    for (int o = 16; o > 0; o >>= 1)
        m = fmaxf(m, __shfl_xor_sync(0xffffffffu, m, o));
    if ((tid & 31) == 0) red[tid >> 5] = m;
    __syncthreads();
    m = red[0];
#pragma unroll
    for (int i = 1; i < 8; i++) m = fmaxf(m, red[i]);

    float s = 0.0f;
#pragma unroll
    for (int i = 0; i < 4; i++) {
        v[i].x = __expf(v[i].x - m);
        v[i].y = __expf(v[i].y - m);
        s += v[i].x + v[i].y;
    }
#pragma unroll
    for (int o = 16; o > 0; o >>= 1)
        s += __shfl_xor_sync(0xffffffffu, s, o);
    __syncthreads();
    if ((tid & 31) == 0) red[tid >> 5] = s;
    __syncthreads();
    s = red[0];
#pragma unroll
    for (int i = 1; i < 8; i++) s += red[i];

    const float inv = 1.0f / s;
    fp16* o = Sf + (long)blockIdx.x * L_;
#pragma unroll
    for (int i = 0; i < 4; i++)
        ((__half2*)o)[i * 256 + tid] = __floats2half2_rn(v[i].x * inv, v[i].y * inv);
}

// ---------------------------------------------------------------------------
// Launch (graph-capturable, allocation-free, single stream).
//   1) K = H @ Wk^T    (fp32 A, fp32 B -> fp16 K)    M=32768, N=256, K=1280
//   2) Q = G @ Wq^T    (fp32 A, fp32 B -> fp16 Q)    M=8192,  N=256, K=768
//   3) S = scale*Q@K^T (fp16, fp16 -> fp32)          per b: 512x2048x256
//   4) softmax -> fp16 probs
//   5) Z = A @ H       (fp16 A, fp32 B NN -> fp32)   per b: 512x1280x2048
// ---------------------------------------------------------------------------
extern "C" void kernel_launch(void* const* d_in, const int* in_sizes, int n_in,
                              void* d_out, int out_size)
{
    const float* H  = (const float*)d_in[0];  // [B, L, DH]
    const float* G  = (const float*)d_in[1];  // [B, T, DG]
    const float* Wq = (const float*)d_in[2];  // [P, DG]
    const float* Wk = (const float*)d_in[3];  // [P, DH]
    float* Z = (float*)d_out;                 // [B, T, DH]

    fp16 *Kf, *Qf, *Sf;
    float* S;
    cudaGetSymbolAddress((void**)&Kf, g_Kf);
    cudaGetSymbolAddress((void**)&Qf, g_Qf);
    cudaGetSymbolAddress((void**)&Sf, g_Sf);
    cudaGetSymbolAddress((void**)&S,  g_S);

    cudaFuncSetAttribute((const void*)gemm_fp16<1, true, true, true>,
                         cudaFuncAttributeMaxDynamicSharedMemorySize, SMEM_NT);
    cudaFuncSetAttribute((const void*)gemm_fp16<0, true, false, false>,
                         cudaFuncAttributeMaxDynamicSharedMemorySize, SMEM_NT);
    cudaFuncSetAttribute((const void*)gemm_fp16<0, false, false, true>,
                         cudaFuncAttributeMaxDynamicSharedMemorySize, SMEM_NN);

    dim3 blk(256);

    // 1) K-projection (convert-in-staging from fp32)
    gemm_fp16<1, true, true, true>
        <<<dim3(P_ / BN, (B_ * L_) / BM, 1), blk, SMEM_NT>>>(
        H, Wk, nullptr, Kf, DH, P_, 0, 0, 0, 1.0f);

    // 2) Q-projection (convert-in-staging from fp32)
    gemm_fp16<1, true, true, true>
        <<<dim3(P_ / BN, (B_ * T_) / BM, 1), blk, SMEM_NT>>>(
        G, Wq, nullptr, Qf, DG, P_, 0, 0, 0, 1.0f);

    // 3) logits (fp16 inputs via cp.async)
    gemm_fp16<0, true, false, false>
        <<<dim3(L_ / BN, T_ / BM, B_), blk, SMEM_NT>>>(
        Qf, Kf, S, nullptr, P_, L_,
        (long)T_ * P_, (long)L_ * P_, (long)T_ * L_, SCALE_);

    // 4) softmax -> fp16 probs
    softmax_rows<<<B_ * T_, blk>>>(S, Sf);

    // 5) Z = A @ H (A fp16 cp.async; B = fp32 H converted in staging, NN)
    gemm_fp16<0, false, false, true>
        <<<dim3(DH / BN, T_ / BM, B_), blk, SMEM_NN>>>(
        Sf, H, Z, nullptr, L_, DH,
        (long)T_ * L_, (long)L_ * DH, (long)T_ * DH, 1.0f);
}

// round 11
// speedup vs baseline: 1.1066x; 1.1066x over previous
#include <cuda_runtime.h>
#include <cuda_fp16.h>
#include <math_constants.h>
#include <cstdint>

// Problem dims (fixed by the reference)
#define B_  16
#define L_  2048
#define DH  1280
#define T_  512
#define DG  768
#define P_  256
#define SCALE_ 0.0625f   // 256^-0.5

typedef __half fp16;

// ---------------- device-global scratch (allocation-free rule) --------------
__device__ __align__(16) fp16 g_Kf [(long)B_ * L_ * P_];   // K fp16
__device__ __align__(16) fp16 g_Qf [(long)B_ * T_ * P_];   // Q fp16
__device__ __align__(16) float g_S [(long)B_ * T_ * L_];   // logits fp32
__device__ __align__(16) fp16 g_Sf [(long)B_ * T_ * L_];   // probs fp16

// ---------------------------------------------------------------------------
// fp16 tensor-core GEMM.
//   CVT_A/CVT_B = true : operand fp32 in gmem. Staged via REGISTER PREFETCH:
//     raw float4 loads issue at k-loop top, conversion+smem store happens
//     after the MMA burst (loads ride the MMA shadow; R10's synchronous
//     ld->cvt->st serialization is avoided).
//             = false  : operand already fp16; staged via cp.async.cg.
//   TRANS_B = true : C = alpha * A[M,K] @ B[N,K]^T   (NT; K-major)
//   TRANS_B = false: C = alpha * A[M,K] @ B[K,N]     (NN; ldmatrix.trans)
//   fp32 accumulate. EPI=0: fp32 C (alpha applied). EPI=1: fp16 C.
// BM=128, BN=128, BK=64, 256 threads = 8 warps (2M x 4N), warp tile 64x32,
// double-buffered smem. CVT variants run 1 CTA/SM (prefetch regs), pure-fp16
// variants 2 CTAs/SM.
// ---------------------------------------------------------------------------
#define BM 128
#define BN 128
#define BK 64
#define SK 72                      // NT row stride (halves)
#define BNP 136                    // NN B row stride (halves), 272B
#define STAGE_A (BM * SK)          // 9216 halves
#define STAGE_B_NT (BN * SK)       // 9216
#define STAGE_B_NN (BK * BNP)      // 8704
#define BUF_NT (STAGE_A + STAGE_B_NT)
#define BUF_NN (STAGE_A + STAGE_B_NN)
#define SMEM_NT (2 * BUF_NT * 2)   // 73728 B
#define SMEM_NN (2 * BUF_NN * 2)   // 71680 B

__device__ __forceinline__ uint32_t smem_a32(const void* p) {
    return (uint32_t)__cvta_generic_to_shared(p);
}

__device__ __forceinline__ void cpa16(uint32_t d, const void* s) {
    asm volatile("cp.async.cg.shared.global [%0], [%1], 16;" :: "r"(d), "l"(s));
}
__device__ __forceinline__ void cpa_commit() {
    asm volatile("cp.async.commit_group;" ::: "memory");
}
__device__ __forceinline__ void cpa_wait0() {
    asm volatile("cp.async.wait_group 0;" ::: "memory");
}

// pack 8 fp32 (two float4) -> 16B of fp16
__device__ __forceinline__ uint4 pack8(const float4& a, const float4& b) {
    __half2 h0 = __floats2half2_rn(a.x, a.y);
    __half2 h1 = __floats2half2_rn(a.z, a.w);
    __half2 h2 = __floats2half2_rn(b.x, b.y);
    __half2 h3 = __floats2half2_rn(b.z, b.w);
    uint4 v;
    v.x = *(uint32_t*)&h0; v.y = *(uint32_t*)&h1;
    v.z = *(uint32_t*)&h2; v.w = *(uint32_t*)&h3;
    return v;
}

__device__ __forceinline__ void ldm4(uint32_t a, uint32_t& r0, uint32_t& r1,
                                     uint32_t& r2, uint32_t& r3) {
    asm volatile("ldmatrix.sync.aligned.m8n8.x4.shared.b16 {%0,%1,%2,%3}, [%4];\n"
                 : "=r"(r0), "=r"(r1), "=r"(r2), "=r"(r3) : "r"(a));
}
__device__ __forceinline__ void ldm4t(uint32_t a, uint32_t& r0, uint32_t& r1,
                                      uint32_t& r2, uint32_t& r3) {
    asm volatile("ldmatrix.sync.aligned.m8n8.x4.trans.shared.b16 {%0,%1,%2,%3}, [%4];\n"
                 : "=r"(r0), "=r"(r1), "=r"(r2), "=r"(r3) : "r"(a));
}

__device__ __forceinline__ void mma16816(float* c, const uint32_t* a,
                                         uint32_t b0, uint32_t b1) {
    asm volatile(
        "mma.sync.aligned.m16n8k16.row.col.f32.f16.f16.f32 "
        "{%0,%1,%2,%3}, {%4,%5,%6,%7}, {%8,%9}, {%0,%1,%2,%3};\n"
        : "+f"(c[0]), "+f"(c[1]), "+f"(c[2]), "+f"(c[3])
        : "r"(a[0]), "r"(a[1]), "r"(a[2]), "r"(a[3]), "r"(b0), "r"(b1));
}

template <int EPI, bool TRANS_B, bool CVT_A, bool CVT_B>
__global__ void __launch_bounds__(256, (CVT_A || CVT_B) ? 1 : 2)
gemm_fp16(const void* __restrict__ Av, const void* __restrict__ Bv,
          float* __restrict__ Cf, fp16* __restrict__ Ch,
          int K, int N, long sA, long sB, long sC, float alpha)
{
    constexpr int BUF = TRANS_B ? BUF_NT : BUF_NN;
    constexpr bool USE_CPA = (!CVT_A) || (!CVT_B);
    extern __shared__ fp16 sm[];   // [2][BUF]

    const long bz = blockIdx.z;
    const float* Af = (const float*)Av + (CVT_A ? bz * sA : 0);
    const fp16*  Ah = (const fp16*)Av + (CVT_A ? 0 : bz * sA);
    const float* Bf = (const float*)Bv + (CVT_B ? bz * sB : 0);
    const fp16*  Bh = (const fp16*)Bv + (CVT_B ? 0 : bz * sB);

    const int m0 = blockIdx.y * BM;
    const int n0 = blockIdx.x * BN;

    const int tid  = threadIdx.x;
    const int lane = tid & 31;
    const int wid  = tid >> 5;
    const int wm = (wid & 1) * 64;    // warp M offset
    const int wn = (wid >> 1) * 32;   // warp N offset

    const int srow = tid >> 3;        // 0..31 (+ i*32)
    const int scc  = (tid & 7) * 8;   // element offset within row

    float acc[4][4][4];
#pragma unroll
    for (int i = 0; i < 4; i++)
#pragma unroll
        for (int j = 0; j < 4; j++)
#pragma unroll
            for (int q = 0; q < 4; q++) acc[i][j][q] = 0.0f;

    float4 pa[8], pb[8];              // prefetch regs (CVT operands only)

    const uint32_t smBase = smem_a32(sm);
    const uint32_t aBase = smBase +
        (uint32_t)(((wm + (lane & 15)) * SK + (lane >> 4) * 8) * 2);
    const int bg = lane >> 3, br = lane & 7;
    const uint32_t bBaseNT = smBase + (uint32_t)(STAGE_A * 2) +
        (uint32_t)(((wn + (bg >> 1) * 8 + br) * SK + (bg & 1) * 8) * 2);
    const uint32_t bBaseNN = smBase + (uint32_t)(STAGE_A * 2) +
        (uint32_t)((((bg & 1) * 8 + br) * BNP + wn + (bg >> 1) * 8) * 2);

    const int nk = K / BK;

    // ---- issue phase: fp32 loads -> regs; fp16 -> cp.async into buf ----
    auto stage_issue = [&](int kt, int buf) {
        const long k0 = (long)kt * BK;
        const uint32_t dA = smBase + (uint32_t)(buf * BUF * 2);
        if (CVT_A) {
#pragma unroll
            for (int i = 0; i < 4; i++) {
                const float* s = Af + (long)(m0 + srow + i * 32) * K + k0 + scc;
                pa[2 * i]     = *(const float4*)s;
                pa[2 * i + 1] = *(const float4*)(s + 4);
            }
        } else {
#pragma unroll
            for (int i = 0; i < 4; i++)
                cpa16(dA + (uint32_t)(((srow + i * 32) * SK + scc) * 2),
                      Ah + (long)(m0 + srow + i * 32) * K + k0 + scc);
        }
        const uint32_t dB = dA + (uint32_t)(STAGE_A * 2);
        if (TRANS_B) {
            if (CVT_B) {
#pragma unroll
                for (int i = 0; i < 4; i++) {
                    const float* s = Bf + (long)(n0 + srow + i * 32) * K + k0 + scc;
                    pb[2 * i]     = *(const float4*)s;
                    pb[2 * i + 1] = *(const float4*)(s + 4);
                }
            } else {
#pragma unroll
                for (int i = 0; i < 4; i++)
                    cpa16(dB + (uint32_t)(((srow + i * 32) * SK + scc) * 2),
                          Bh + (long)(n0 + srow + i * 32) * K + k0 + scc);
            }
        } else {
            // B tile [BK=64 rows][128 elems] = 1024 chunks, 4/thread
            if (CVT_B) {
#pragma unroll
                for (int i = 0; i < 4; i++) {
                    const int ch = tid + i * 256;
                    const int kr = ch >> 4;
                    const int nc = (ch & 15) * 8;
                    const float* s = Bf + (k0 + kr) * (long)N + n0 + nc;
                    pb[2 * i]     = *(const float4*)s;
                    pb[2 * i + 1] = *(const float4*)(s + 4);
                }
            } else {
#pragma unroll
                for (int i = 0; i < 4; i++) {
                    const int ch = tid + i * 256;
                    const int kr = ch >> 4;
                    const int nc = (ch & 15) * 8;
                    cpa16(dB + (uint32_t)((kr * BNP + nc) * 2),
                          Bh + (k0 + kr) * (long)N + n0 + nc);
                }
            }
        }
    };

    // ---- store phase: convert prefetched fp32 regs -> smem fp16 ----
    auto stage_store = [&](int buf) {
        fp16* dstA = sm + buf * BUF;
        if (CVT_A) {
#pragma unroll
            for (int i = 0; i < 4; i++)
                *(uint4*)(dstA + (srow + i * 32) * SK + scc) =
                    pack8(pa[2 * i], pa[2 * i + 1]);
        }
        if (CVT_B) {
            fp16* dstB = dstA + STAGE_A;
            if (TRANS_B) {
#pragma unroll
                for (int i = 0; i < 4; i++)
                    *(uint4*)(dstB + (srow + i * 32) * SK + scc) =
                        pack8(pb[2 * i], pb[2 * i + 1]);
            } else {
#pragma unroll
                for (int i = 0; i < 4; i++) {
                    const int ch = tid + i * 256;
                    const int kr = ch >> 4;
                    const int nc = (ch & 15) * 8;
                    *(uint4*)(dstB + kr * BNP + nc) =
                        pack8(pb[2 * i], pb[2 * i + 1]);
                }
            }
        }
    };

    // prologue
    stage_issue(0, 0);
    stage_store(0);
    if (USE_CPA) { cpa_commit(); cpa_wait0(); }
    __syncthreads();

    for (int kt = 0; kt < nk; kt++) {
        const int cur = kt & 1;
        const bool more = (kt + 1 < nk);
        if (more) {
            stage_issue(kt + 1, 1 - cur);   // loads issue; nothing consumes yet
            if (USE_CPA) cpa_commit();
        }

        const uint32_t bufOff = (uint32_t)(cur * (BUF * 2));
#pragma unroll
        for (int ks = 0; ks < 4; ks++) {
            uint32_t af[4][4], bf[2][4];
#pragma unroll
            for (int fm = 0; fm < 4; fm++)
                ldm4(aBase + bufOff + (uint32_t)(fm * (16 * SK * 2) + ks * 32),
                     af[fm][0], af[fm][1], af[fm][2], af[fm][3]);
            if (TRANS_B) {
#pragma unroll
                for (int f2 = 0; f2 < 2; f2++)
                    ldm4(bBaseNT + bufOff + (uint32_t)(f2 * (16 * SK * 2) + ks * 32),
                         bf[f2][0], bf[f2][1], bf[f2][2], bf[f2][3]);
            } else {
#pragma unroll
                for (int f2 = 0; f2 < 2; f2++)
                    ldm4t(bBaseNN + bufOff +
                              (uint32_t)(ks * (16 * BNP * 2) + f2 * 32),
                          bf[f2][0], bf[f2][1], bf[f2][2], bf[f2][3]);
            }
#pragma unroll
            for (int fm = 0; fm < 4; fm++)
#pragma unroll
                for (int fn = 0; fn < 4; fn++)
                    mma16816(acc[fm][fn], af[fm],
                             bf[fn >> 1][(fn & 1) * 2],
                             bf[fn >> 1][(fn & 1) * 2 + 1]);
        }

        if (more) {
            stage_store(1 - cur);           // consume prefetched regs post-MMA
            if (USE_CPA) cpa_wait0();
        }
        __syncthreads();
    }

    const int er = lane >> 2, ec = (lane & 3) * 2;
    if (EPI == 0) Cf += bz * sC; else Ch += bz * sC;
#pragma unroll
    for (int fm = 0; fm < 4; fm++) {
#pragma unroll
        for (int fn = 0; fn < 4; fn++) {
            const int row = m0 + wm + fm * 16 + er;
            const int col = n0 + wn + fn * 8 + ec;
            if (EPI == 0) {
                float2 v0 = {acc[fm][fn][0] * alpha, acc[fm][fn][1] * alpha};
                float2 v1 = {acc[fm][fn][2] * alpha, acc[fm][fn][3] * alpha};
                *(float2*)(Cf + (long)row * N + col) = v0;
                *(float2*)(Cf + (long)(row + 8) * N + col) = v1;
            } else {
                __half2 v0 = __floats2half2_rn(acc[fm][fn][0], acc[fm][fn][1]);
                __half2 v1 = __floats2half2_rn(acc[fm][fn][2], acc[fm][fn][3]);
                *(__half2*)(Ch + (long)row * N + col) = v0;
                *(__half2*)(Ch + (long)(row + 8) * N + col) = v1;
            }
        }
    }
}

// ---------------------------------------------------------------------------
// Row softmax over L_=2048 (fp32 logits in, fp16 probs out).
// ---------------------------------------------------------------------------
__global__ void __launch_bounds__(256)
softmax_rows(const float* __restrict__ S, fp16* __restrict__ Sf)
{
    const float* p = S + (long)blockIdx.x * L_;
    const int tid = threadIdx.x;

    float2 v[4];
    float m = -CUDART_INF_F;
#pragma unroll
    for (int i = 0; i < 4; i++) {
        v[i] = ((const float2*)p)[i * 256 + tid];
        m = fmaxf(m, fmaxf(v[i].x, v[i].y));
    }

    __shared__ float red[8];
#pragma unroll
    for (int o = 16; o > 0; o >>= 1)
        m = fmaxf(m, __shfl_xor_sync(0xffffffffu, m, o));
    if ((tid & 31) == 0) red[tid >> 5] = m;
    __syncthreads();
    m = red[0];
#pragma unroll
    for (int i = 1; i < 8; i++) m = fmaxf(m, red[i]);

    float s = 0.0f;
#pragma unroll
    for (int i = 0; i < 4; i++) {
        v[i].x = __expf(v[i].x - m);
        v[i].y = __expf(v[i].y - m);
        s += v[i].x + v[i].y;
    }
#pragma unroll
    for (int o = 16; o > 0; o >>= 1)
        s += __shfl_xor_sync(0xffffffffu, s, o);
    __syncthreads();
    if ((tid & 31) == 0) red[tid >> 5] = s;
    __syncthreads();
    s = red[0];
#pragma unroll
    for (int i = 1; i < 8; i++) s += red[i];

    const float inv = 1.0f / s;
    fp16* o = Sf + (long)blockIdx.x * L_;
#pragma unroll
    for (int i = 0; i < 4; i++)
        ((__half2*)o)[i * 256 + tid] = __floats2half2_rn(v[i].x * inv, v[i].y * inv);
}

// ---------------------------------------------------------------------------
// Launch (graph-capturable, allocation-free, single stream).
// ---------------------------------------------------------------------------
extern "C" void kernel_launch(void* const* d_in, const int* in_sizes, int n_in,
                              void* d_out, int out_size)
{
    const float* H  = (const float*)d_in[0];  // [B, L, DH]
    const float* G  = (const float*)d_in[1];  // [B, T, DG]
    const float* Wq = (const float*)d_in[2];  // [P, DG]
    const float* Wk = (const float*)d_in[3];  // [P, DH]
    float* Z = (float*)d_out;                 // [B, T, DH]

    fp16 *Kf, *Qf, *Sf;
    float* S;
    cudaGetSymbolAddress((void**)&Kf, g_Kf);
    cudaGetSymbolAddress((void**)&Qf, g_Qf);
    cudaGetSymbolAddress((void**)&Sf, g_Sf);
    cudaGetSymbolAddress((void**)&S,  g_S);

    cudaFuncSetAttribute((const void*)gemm_fp16<1, true, true, true>,
                         cudaFuncAttributeMaxDynamicSharedMemorySize, SMEM_NT);
    cudaFuncSetAttribute((const void*)gemm_fp16<0, true, false, false>,
                         cudaFuncAttributeMaxDynamicSharedMemorySize, SMEM_NT);
    cudaFuncSetAttribute((const void*)gemm_fp16<0, false, false, true>,
                         cudaFuncAttributeMaxDynamicSharedMemorySize, SMEM_NN);

    dim3 blk(256);

    // 1) K = H @ Wk^T (fp32 inputs, convert-in-staging w/ register prefetch)
    gemm_fp16<1, true, true, true>
        <<<dim3(P_ / BN, (B_ * L_) / BM, 1), blk, SMEM_NT>>>(
        H, Wk, nullptr, Kf, DH, P_, 0, 0, 0, 1.0f);

    // 2) Q = G @ Wq^T (fp32 inputs, convert-in-staging)
    gemm_fp16<1, true, true, true>
        <<<dim3(P_ / BN, (B_ * T_) / BM, 1), blk, SMEM_NT>>>(
        G, Wq, nullptr, Qf, DG, P_, 0, 0, 0, 1.0f);

    // 3) logits (fp16 inputs via cp.async, 2 CTA/SM)
    gemm_fp16<0, true, false, false>
        <<<dim3(L_ / BN, T_ / BM, B_), blk, SMEM_NT>>>(
        Qf, Kf, S, nullptr, P_, L_,
        (long)T_ * P_, (long)L_ * P_, (long)T_ * L_, SCALE_);

    // 4) softmax -> fp16 probs
    softmax_rows<<<B_ * T_, blk>>>(S, Sf);

    // 5) Z = A @ H (A fp16 cp.async; B = fp32 H register-prefetch cvt, NN)
    gemm_fp16<0, false, false, true>
        <<<dim3(DH / BN, T_ / BM, B_), blk, SMEM_NN>>>(
        Sf, H, Z, nullptr, L_, DH,
        (long)T_ * L_, (long)L_ * DH, (long)T_ * DH, 1.0f);
}

// round 12
// speedup vs baseline: 1.3188x; 1.1917x over previous
#include <cuda_runtime.h>
#include <cuda_fp16.h>
#include <math_constants.h>
#include <cstdint>

// Problem dims (fixed by the reference)
#define B_  16
#define L_  2048
#define DH  1280
#define T_  512
#define DG  768
#define P_  256
#define SCALE_ 0.0625f   // 256^-0.5

typedef __half fp16;

// ---------------- device-global scratch (allocation-free rule) --------------
__device__ __align__(16) fp16 g_Hf [(long)B_ * L_ * DH];   // H  fp16 [b,l,d]
__device__ __align__(16) fp16 g_Gf [(long)B_ * T_ * DG];
__device__ __align__(16) fp16 g_Wqf[P_ * DG];
__device__ __align__(16) fp16 g_Wkf[P_ * DH];
__device__ __align__(16) fp16 g_Kf [(long)B_ * L_ * P_];   // K fp16
__device__ __align__(16) fp16 g_Qf [(long)B_ * T_ * P_];   // Q fp16
__device__ __align__(16) fp16 g_Sl [(long)B_ * T_ * L_];   // logits fp16
__device__ __align__(16) fp16 g_Sf [(long)B_ * T_ * L_];   // probs fp16

// ---------------------------------------------------------------------------
// fp16 tensor-core GEMM, cp.async double-buffered, 2 CTAs/SM. (R7 config)
//   TRANS_B = true : C = alpha * A[M,K] @ B[N,K]^T   (NT; both K-major)
//   TRANS_B = false: C = alpha * A[M,K] @ B[K,N]     (NN; ldmatrix.trans)
//   fp32 accumulate. EPI=0: fp32 C. EPI=1: fp16 C. alpha applied in both.
// BM=128, BN=128, BK=64, 256 threads = 8 warps (2M x 4N), warp tile 64x32.
// ---------------------------------------------------------------------------
#define BM 128
#define BN 128
#define BK 64
#define SK 72                      // NT row stride (halves)
#define BNP 136                    // NN B row stride (halves), 272B
#define STAGE_A (BM * SK)          // 9216 halves
#define STAGE_B_NT (BN * SK)       // 9216
#define STAGE_B_NN (BK * BNP)      // 8704
#define BUF_NT (STAGE_A + STAGE_B_NT)
#define BUF_NN (STAGE_A + STAGE_B_NN)
#define SMEM_NT (2 * BUF_NT * 2)   // 73728 B
#define SMEM_NN (2 * BUF_NN * 2)   // 71680 B

__device__ __forceinline__ uint32_t smem_a32(const void* p) {
    return (uint32_t)__cvta_generic_to_shared(p);
}

__device__ __forceinline__ void cpa16(uint32_t d, const void* s) {
    asm volatile("cp.async.cg.shared.global [%0], [%1], 16;" :: "r"(d), "l"(s));
}
__device__ __forceinline__ void cpa_commit() {
    asm volatile("cp.async.commit_group;" ::: "memory");
}
__device__ __forceinline__ void cpa_wait0() {
    asm volatile("cp.async.wait_group 0;" ::: "memory");
}

__device__ __forceinline__ void ldm4(uint32_t a, uint32_t& r0, uint32_t& r1,
                                     uint32_t& r2, uint32_t& r3) {
    asm volatile("ldmatrix.sync.aligned.m8n8.x4.shared.b16 {%0,%1,%2,%3}, [%4];\n"
                 : "=r"(r0), "=r"(r1), "=r"(r2), "=r"(r3) : "r"(a));
}
__device__ __forceinline__ void ldm4t(uint32_t a, uint32_t& r0, uint32_t& r1,
                                      uint32_t& r2, uint32_t& r3) {
    asm volatile("ldmatrix.sync.aligned.m8n8.x4.trans.shared.b16 {%0,%1,%2,%3}, [%4];\n"
                 : "=r"(r0), "=r"(r1), "=r"(r2), "=r"(r3) : "r"(a));
}

__device__ __forceinline__ void mma16816(float* c, const uint32_t* a,
                                         uint32_t b0, uint32_t b1) {
    asm volatile(
        "mma.sync.aligned.m16n8k16.row.col.f32.f16.f16.f32 "
        "{%0,%1,%2,%3}, {%4,%5,%6,%7}, {%8,%9}, {%0,%1,%2,%3};\n"
        : "+f"(c[0]), "+f"(c[1]), "+f"(c[2]), "+f"(c[3])
        : "r"(a[0]), "r"(a[1]), "r"(a[2]), "r"(a[3]), "r"(b0), "r"(b1));
}

template <int EPI, bool TRANS_B>
__global__ void __launch_bounds__(256, 2)
gemm_fp16(const fp16* __restrict__ A, const fp16* __restrict__ Bm,
          float* __restrict__ Cf, fp16* __restrict__ Ch,
          int K, int N, long sA, long sB, long sC, float alpha)
{
    constexpr int BUF = TRANS_B ? BUF_NT : BUF_NN;
    extern __shared__ fp16 sm[];   // [2][BUF]

    const long bz = blockIdx.z;
    A  += bz * sA;
    Bm += bz * sB;
    const int m0 = blockIdx.y * BM;
    const int n0 = blockIdx.x * BN;

    const int tid  = threadIdx.x;
    const int lane = tid & 31;
    const int wid  = tid >> 5;
    const int wm = (wid & 1) * 64;    // warp M offset
    const int wn = (wid >> 1) * 32;   // warp N offset

    const int srow = tid >> 3;        // 0..31 (+ i*32)
    const int scc  = (tid & 7) * 8;   // half offset within row

    float acc[4][4][4];
#pragma unroll
    for (int i = 0; i < 4; i++)
#pragma unroll
        for (int j = 0; j < 4; j++)
#pragma unroll
            for (int q = 0; q < 4; q++) acc[i][j][q] = 0.0f;

    const uint32_t smBase = smem_a32(sm);
    const uint32_t aBase = smBase +
        (uint32_t)(((wm + (lane & 15)) * SK + (lane >> 4) * 8) * 2);
    const int bg = lane >> 3, br = lane & 7;
    const uint32_t bBaseNT = smBase + (uint32_t)(STAGE_A * 2) +
        (uint32_t)(((wn + (bg >> 1) * 8 + br) * SK + (bg & 1) * 8) * 2);
    const uint32_t bBaseNN = smBase + (uint32_t)(STAGE_A * 2) +
        (uint32_t)((((bg & 1) * 8 + br) * BNP + wn + (bg >> 1) * 8) * 2);

    const int nk = K / BK;

    auto stage = [&](int kt, int buf) {
        const long k0 = (long)kt * BK;
        const uint32_t dA = smBase + (uint32_t)(buf * BUF * 2);
#pragma unroll
        for (int i = 0; i < 4; i++)
            cpa16(dA + (uint32_t)(((srow + i * 32) * SK + scc) * 2),
                  A + (long)(m0 + srow + i * 32) * K + k0 + scc);
        const uint32_t dB = dA + (uint32_t)(STAGE_A * 2);
        if (TRANS_B) {
#pragma unroll
            for (int i = 0; i < 4; i++)
                cpa16(dB + (uint32_t)(((srow + i * 32) * SK + scc) * 2),
                      Bm + (long)(n0 + srow + i * 32) * K + k0 + scc);
        } else {
#pragma unroll
            for (int i = 0; i < 4; i++) {
                const int ch = tid + i * 256;
                const int kr = ch >> 4;          // 0..63
                const int nc = (ch & 15) * 8;    // 0..120
                cpa16(dB + (uint32_t)((kr * BNP + nc) * 2),
                      Bm + (k0 + kr) * (long)N + n0 + nc);
            }
        }
    };

    stage(0, 0);
    cpa_commit();
    cpa_wait0();
    __syncthreads();

    for (int kt = 0; kt < nk; kt++) {
        const int cur = kt & 1;
        const bool more = (kt + 1 < nk);
        if (more) {
            stage(kt + 1, 1 - cur);
            cpa_commit();
        }

        const uint32_t bufOff = (uint32_t)(cur * (BUF * 2));
#pragma unroll
        for (int ks = 0; ks < 4; ks++) {
            uint32_t af[4][4], bf[2][4];
#pragma unroll
            for (int fm = 0; fm < 4; fm++)
                ldm4(aBase + bufOff + (uint32_t)(fm * (16 * SK * 2) + ks * 32),
                     af[fm][0], af[fm][1], af[fm][2], af[fm][3]);
            if (TRANS_B) {
#pragma unroll
                for (int f2 = 0; f2 < 2; f2++)
                    ldm4(bBaseNT + bufOff + (uint32_t)(f2 * (16 * SK * 2) + ks * 32),
                         bf[f2][0], bf[f2][1], bf[f2][2], bf[f2][3]);
            } else {
#pragma unroll
                for (int f2 = 0; f2 < 2; f2++)
                    ldm4t(bBaseNN + bufOff +
                              (uint32_t)(ks * (16 * BNP * 2) + f2 * 32),
                          bf[f2][0], bf[f2][1], bf[f2][2], bf[f2][3]);
            }
#pragma unroll
            for (int fm = 0; fm < 4; fm++)
#pragma unroll
                for (int fn = 0; fn < 4; fn++)
                    mma16816(acc[fm][fn], af[fm],
                             bf[fn >> 1][(fn & 1) * 2],
                             bf[fn >> 1][(fn & 1) * 2 + 1]);
        }

        if (more) cpa_wait0();
        __syncthreads();
    }

    const int er = lane >> 2, ec = (lane & 3) * 2;
    if (EPI == 0) Cf += bz * sC; else Ch += bz * sC;
#pragma unroll
    for (int fm = 0; fm < 4; fm++) {
#pragma unroll
        for (int fn = 0; fn < 4; fn++) {
            const int row = m0 + wm + fm * 16 + er;
            const int col = n0 + wn + fn * 8 + ec;
            if (EPI == 0) {
                float2 v0 = {acc[fm][fn][0] * alpha, acc[fm][fn][1] * alpha};
                float2 v1 = {acc[fm][fn][2] * alpha, acc[fm][fn][3] * alpha};
                *(float2*)(Cf + (long)row * N + col) = v0;
                *(float2*)(Cf + (long)(row + 8) * N + col) = v1;
            } else {
                __half2 v0 = __floats2half2_rn(acc[fm][fn][0] * alpha,
                                               acc[fm][fn][1] * alpha);
                __half2 v1 = __floats2half2_rn(acc[fm][fn][2] * alpha,
                                               acc[fm][fn][3] * alpha);
                *(__half2*)(Ch + (long)row * N + col) = v0;
                *(__half2*)(Ch + (long)(row + 8) * N + col) = v1;
            }
        }
    }
}

// ---------------------------------------------------------------------------
// Fused fp32 -> fp16 conversion of all four inputs in ONE launch.
// Segments run back-to-back with full grid participation (kills the tiny-grid
// latency of separate W conversions).
// ---------------------------------------------------------------------------
__device__ __forceinline__ void conv_seg(const float* __restrict__ x,
                                         fp16* __restrict__ y, long n4,
                                         long gid, long gstride)
{
    for (long i = gid; i < n4; i += gstride) {
        const float4 v = ((const float4*)x)[i];
        __half2 a = __floats2half2_rn(v.x, v.y);
        __half2 b = __floats2half2_rn(v.z, v.w);
        uint2 o = {*(uint32_t*)&a, *(uint32_t*)&b};
        ((uint2*)y)[i] = o;
    }
}

__global__ void __launch_bounds__(256)
conv_all(const float* __restrict__ H,  fp16* __restrict__ Hf,
         const float* __restrict__ G,  fp16* __restrict__ Gf,
         const float* __restrict__ Wq, fp16* __restrict__ Wqf,
         const float* __restrict__ Wk, fp16* __restrict__ Wkf)
{
    const long gid = blockIdx.x * (long)blockDim.x + threadIdx.x;
    const long gstride = (long)gridDim.x * blockDim.x;
    conv_seg(Wq, Wqf, (long)P_ * DG / 4, gid, gstride);
    conv_seg(Wk, Wkf, (long)P_ * DH / 4, gid, gstride);
    conv_seg(G,  Gf,  (long)B_ * T_ * DG / 4, gid, gstride);
    conv_seg(H,  Hf,  (long)B_ * L_ * DH / 4, gid, gstride);
}

// ---------------------------------------------------------------------------
// Row softmax over L_=2048 (fp16 logits in, fp16 probs out).
// ---------------------------------------------------------------------------
__global__ void __launch_bounds__(256)
softmax_rows(const fp16* __restrict__ Sl, fp16* __restrict__ Sf)
{
    const fp16* p = Sl + (long)blockIdx.x * L_;
    const int tid = threadIdx.x;

    float2 v[4];
    float m = -CUDART_INF_F;
#pragma unroll
    for (int i = 0; i < 4; i++) {
        const __half2 h = ((const __half2*)p)[i * 256 + tid];
        v[i] = __half22float2(h);
        m = fmaxf(m, fmaxf(v[i].x, v[i].y));
    }

    __shared__ float red[8];
#pragma unroll
    for (int o = 16; o > 0; o >>= 1)
        m = fmaxf(m, __shfl_xor_sync(0xffffffffu, m, o));
    if ((tid & 31) == 0) red[tid >> 5] = m;
    __syncthreads();
    m = red[0];
#pragma unroll
    for (int i = 1; i < 8; i++) m = fmaxf(m, red[i]);

    float s = 0.0f;
#pragma unroll
    for (int i = 0; i < 4; i++) {
        v[i].x = __expf(v[i].x - m);
        v[i].y = __expf(v[i].y - m);
        s += v[i].x + v[i].y;
    }
#pragma unroll
    for (int o = 16; o > 0; o >>= 1)
        s += __shfl_xor_sync(0xffffffffu, s, o);
    __syncthreads();
    if ((tid & 31) == 0) red[tid >> 5] = s;
    __syncthreads();
    s = red[0];
#pragma unroll
    for (int i = 1; i < 8; i++) s += red[i];

    const float inv = 1.0f / s;
    fp16* o = Sf + (long)blockIdx.x * L_;
#pragma unroll
    for (int i = 0; i < 4; i++)
        ((__half2*)o)[i * 256 + tid] = __floats2half2_rn(v[i].x * inv, v[i].y * inv);
}

// ---------------------------------------------------------------------------
// Launch (graph-capturable, allocation-free, single stream).
//   0) conv_all: H,G,Wq,Wk fp32 -> fp16 (one launch)
//   1) K = H @ Wk^T    M=32768, N=256, K=1280  -> fp16 (NT)
//   2) Q = G @ Wq^T    M=8192,  N=256, K=768   -> fp16 (NT)
//   3) Slog = scale*Q@K^T per b: 512x2048x256  -> fp16 logits (NT)
//   4) softmax (fp16 in/out)
//   5) Z = A @ H       per b: 512x1280x2048    -> fp32 (NN)
// ---------------------------------------------------------------------------
extern "C" void kernel_launch(void* const* d_in, const int* in_sizes, int n_in,
                              void* d_out, int out_size)
{
    const float* H  = (const float*)d_in[0];  // [B, L, DH]
    const float* G  = (const float*)d_in[1];  // [B, T, DG]
    const float* Wq = (const float*)d_in[2];  // [P, DG]
    const float* Wk = (const float*)d_in[3];  // [P, DH]
    float* Z = (float*)d_out;                 // [B, T, DH]

    fp16 *Hf, *Gf, *Wqf, *Wkf, *Kf, *Qf, *Sl, *Sf;
    cudaGetSymbolAddress((void**)&Hf,  g_Hf);
    cudaGetSymbolAddress((void**)&Gf,  g_Gf);
    cudaGetSymbolAddress((void**)&Wqf, g_Wqf);
    cudaGetSymbolAddress((void**)&Wkf, g_Wkf);
    cudaGetSymbolAddress((void**)&Kf,  g_Kf);
    cudaGetSymbolAddress((void**)&Qf,  g_Qf);
    cudaGetSymbolAddress((void**)&Sl,  g_Sl);
    cudaGetSymbolAddress((void**)&Sf,  g_Sf);

    cudaFuncSetAttribute((const void*)gemm_fp16<1, true>,
                         cudaFuncAttributeMaxDynamicSharedMemorySize, SMEM_NT);
    cudaFuncSetAttribute((const void*)gemm_fp16<0, false>,
                         cudaFuncAttributeMaxDynamicSharedMemorySize, SMEM_NN);

    dim3 blk(256);

    // 0) all input conversions in one launch
    conv_all<<<2048, blk>>>(H, Hf, G, Gf, Wq, Wqf, Wk, Wkf);

    // 1) K-projection (NT) -> fp16
    gemm_fp16<1, true><<<dim3(P_ / BN, (B_ * L_) / BM, 1), blk, SMEM_NT>>>(
        Hf, Wkf, nullptr, Kf, DH, P_, 0, 0, 0, 1.0f);

    // 2) Q-projection (NT) -> fp16
    gemm_fp16<1, true><<<dim3(P_ / BN, (B_ * T_) / BM, 1), blk, SMEM_NT>>>(
        Gf, Wqf, nullptr, Qf, DG, P_, 0, 0, 0, 1.0f);

    // 3) logits (NT) -> fp16 (scale applied in epilogue)
    gemm_fp16<1, true><<<dim3(L_ / BN, T_ / BM, B_), blk, SMEM_NT>>>(
        Qf, Kf, nullptr, Sl, P_, L_,
        (long)T_ * P_, (long)L_ * P_, (long)T_ * L_, SCALE_);

    // 4) softmax -> fp16 probs
    softmax_rows<<<B_ * T_, blk>>>(Sl, Sf);

    // 5) Z = A @ H (NN, fp32 out)
    gemm_fp16<0, false><<<dim3(DH / BN, T_ / BM, B_), blk, SMEM_NN>>>(
        Sf, Hf, Z, nullptr, L_, DH,
        (long)T_ * L_, (long)L_ * DH, (long)T_ * DH, 1.0f);
}